// round 12
// baseline (speedup 1.0000x reference)
#include <cuda_runtime.h>

// YOLOV3TargetMerger: b=32, N=22743, M=50, C=80
// Inputs: 0 box_preds[b,N,4] 1 gt_boxes[b,M,4] 2 obj_t[b,N,1]
//         3 centers_t[b,N,2] 4 scales_t[b,N,2] 5 weights_t[b,N,2] 6 clas_t[b,N,80]
// Output (concat f32): obj[S], cen[2S], sca[2S], wei[2S], cls_t[80S], cls_m[80S]
//
// Converged structure: concurrent fork/join of a small per-anchor kernel and a
// streaming class kernel; total time = total DRAM bytes / achieved HBM BW
// (~718 MB @ ~6.9 TB/s). cls reads are predicated (real 116 MB saving);
// bp/cen/sca/wei loads are unconditional (predication saves no DRAM sectors).

#define BATCH 32
#define MGT   50
#define NCLS  80
#define C4    (NCLS / 4)
#define THR   0.7f
#define EPSF  1e-12f
#define CLS_THREADS 256
#define UNROLL 4
#define CHUNK (CLS_THREADS * UNROLL)   // 1024 float4 per block

__global__ void __launch_bounds__(256) merge_main_kernel(
    const float4* __restrict__ bp,
    const float4* __restrict__ gt,
    const float*  __restrict__ obj,
    const float2* __restrict__ cen,
    const float2* __restrict__ sca,
    const float2* __restrict__ wei,
    float* __restrict__ out,
    int N, long long S)
{
    __shared__ float4 sgt[MGT];
    __shared__ float  sarea[MGT];
    __shared__ int    scnt;

    const int b = blockIdx.y;
    const int t = threadIdx.x;

    // compact gt boxes: non-positive width/height => inter==0 vs every anchor,
    // which can never produce a hit (needs d>0, then 0 > 0.7*d is false).
    if (t == 0) scnt = 0;
    __syncthreads();
    if (t < MGT) {
        const float4 g = gt[b * MGT + t];
        if (g.z > g.x && g.w > g.y) {
            const int k = atomicAdd(&scnt, 1);
            sgt[k]   = g;
            sarea[k] = (g.z - g.x) * (g.w - g.y);
        }
    }
    __syncthreads();
    const int K = scnt;                       // ~12.5 expected

    const int n = blockIdx.x * blockDim.x + t;
    if (n >= N) return;
    const long long i = (long long)b * N + n;

    // Unconditional loads: predicating these saves no DRAM sectors (a 128B
    // line spans 8-16 anchors; ~50% random mask touches nearly every line).
    const float  o = obj[i];
    const float4 p = bp[i];
    const float2 c = cen[i];
    const float2 s = sca[i];
    const float2 w = wei[i];
    const bool mask = (o > 0.0f);

    float objout;
    if (mask) {
        objout = o;                           // IOU result unused -> skip loop
    } else {
        const float area_p = (p.z - p.x) * (p.w - p.y);

        bool hit = false, ambig = false;
        for (int m = 0; m < K; m++) {
            const float4 g = sgt[m];
            const float ww = fmaxf(fminf(p.z, g.z) - fmaxf(p.x, g.x), 0.0f);
            const float hh = fmaxf(fminf(p.w, g.w) - fmaxf(p.y, g.y), 0.0f);
            const float inter = ww * hh;
            float u = area_p + sarea[m];
            u = u - inter;
            const float d = u + EPSF;         // ref denominator, same op order
            const float thr  = THR * d;
            const float diff = inter - thr;
            const float marg = 1e-6f * thr;
            const bool pos = (d > 0.0f);
            hit   = hit   | (pos & (diff >  marg));
            ambig = ambig | (pos & (fabsf(diff) <= marg));
        }
        if (ambig) {                          // rare: redo exactly (IEEE div)
            hit = false;
            for (int m = 0; m < K; m++) {
                const float4 g = sgt[m];
                const float ww = fmaxf(fminf(p.z, g.z) - fmaxf(p.x, g.x), 0.0f);
                const float hh = fmaxf(fminf(p.w, g.w) - fmaxf(p.y, g.y), 0.0f);
                const float inter = ww * hh;
                float u = area_p + sarea[m];
                u = u - inter;
                const float d = u + EPSF;
                hit = hit | ((inter / d) > THR);  // d<0 -> iou<=0 -> false (== ref)
            }
        }
        objout = hit ? -1.0f : 0.0f;
    }

    out[i] = objout;

    const float2 z = make_float2(0.0f, 0.0f);
    ((float2*)(out + S     ))[i] = mask ? c : z;
    ((float2*)(out + 3 * S ))[i] = mask ? s : z;
    ((float2*)(out + 5 * S ))[i] = mask ? w : z;
}

// Flat grid, short-lived CTAs, 4 front-batched iterations per thread.
__global__ void __launch_bounds__(CLS_THREADS) merge_class_kernel(
    const float*  __restrict__ obj,
    const float4* __restrict__ cls,
    float4* __restrict__ out_t,
    float4* __restrict__ out_m,
    int total4)   // = S * C4  (14.55M, fits int)
{
    const int base = blockIdx.x * CHUNK + threadIdx.x;

    if (base + (UNROLL - 1) * CLS_THREADS < total4) {
        // full chunk: no bounds checks
        bool   mk[UNROLL];
        float4 c[UNROLL];
#pragma unroll
        for (int j = 0; j < UNROLL; j++)
            mk[j] = (obj[(unsigned)(base + j * CLS_THREADS) / C4] > 0.0f);
#pragma unroll
        for (int j = 0; j < UNROLL; j++)
            c[j] = mk[j] ? __ldcs(&cls[base + j * CLS_THREADS])
                         : make_float4(-1.0f, -1.0f, -1.0f, -1.0f);
#pragma unroll
        for (int j = 0; j < UNROLL; j++) {
            const int idx = base + j * CLS_THREADS;
            float4 mv;
            if (mk[j]) {
                mv.x = (c[j].x >= 0.0f) ? 1.0f : 0.0f;
                mv.y = (c[j].y >= 0.0f) ? 1.0f : 0.0f;
                mv.z = (c[j].z >= 0.0f) ? 1.0f : 0.0f;
                mv.w = (c[j].w >= 0.0f) ? 1.0f : 0.0f;
            } else {
                mv = make_float4(0.0f, 0.0f, 0.0f, 0.0f);
            }
            __stcs(&out_t[idx], c[j]);
            __stcs(&out_m[idx], mv);
        }
    } else {
        // tail block
#pragma unroll
        for (int j = 0; j < UNROLL; j++) {
            const int idx = base + j * CLS_THREADS;
            if (idx >= total4) continue;
            const bool mask = (obj[(unsigned)idx / C4] > 0.0f);
            float4 tv, mv;
            if (mask) {
                const float4 cc = __ldcs(&cls[idx]);
                tv = cc;
                mv.x = (cc.x >= 0.0f) ? 1.0f : 0.0f;
                mv.y = (cc.y >= 0.0f) ? 1.0f : 0.0f;
                mv.z = (cc.z >= 0.0f) ? 1.0f : 0.0f;
                mv.w = (cc.w >= 0.0f) ? 1.0f : 0.0f;
            } else {
                tv = make_float4(-1.0f, -1.0f, -1.0f, -1.0f);
                mv = make_float4(0.0f, 0.0f, 0.0f, 0.0f);
            }
            __stcs(&out_t[idx], tv);
            __stcs(&out_m[idx], mv);
        }
    }
}

static cudaStream_t g_s2 = 0;
static cudaEvent_t  g_fork = 0, g_join = 0;

extern "C" void kernel_launch(void* const* d_in, const int* in_sizes, int n_in,
                              void* d_out, int out_size)
{
    const float4* bp  = (const float4*)d_in[0];
    const float4* gt  = (const float4*)d_in[1];
    const float*  obj = (const float*) d_in[2];
    const float2* cen = (const float2*)d_in[3];
    const float2* sca = (const float2*)d_in[4];
    const float2* wei = (const float2*)d_in[5];
    const float*  cls = (const float*) d_in[6];

    const long long S = in_sizes[2];      // b * N
    const int N = (int)(S / BATCH);
    float* out = (float*)d_out;

    if (g_s2 == 0) {
        cudaStreamCreateWithFlags(&g_s2, cudaStreamNonBlocking);
        cudaEventCreateWithFlags(&g_fork, cudaEventDisableTiming);
        cudaEventCreateWithFlags(&g_join, cudaEventDisableTiming);
    }

    // Fork: main kernel runs concurrently on g_s2 under the class stream.
    cudaEventRecord(g_fork, 0);
    cudaStreamWaitEvent(g_s2, g_fork, 0);

    {   // main path (small) — side stream
        dim3 block(256, 1, 1);
        dim3 grid((N + 255) / 256, BATCH, 1);
        merge_main_kernel<<<grid, block, 0, g_s2>>>(bp, gt, obj, cen, sca, wei,
                                                    out, N, S);
    }
    {   // class path (long pole) — capture/default stream
        const int total4 = (int)(S * C4);
        float4* out_t = (float4*)(out + 7LL  * S);
        float4* out_m = (float4*)(out + 87LL * S);
        const int blocks = (total4 + CHUNK - 1) / CHUNK;
        merge_class_kernel<<<blocks, CLS_THREADS>>>(obj, (const float4*)cls,
                                                    out_t, out_m, total4);
    }

    // Join: default stream waits for the side stream's kernel.
    cudaEventRecord(g_join, g_s2);
    cudaStreamWaitEvent(0, g_join, 0);
}

// round 13
// speedup vs baseline: 1.0003x; 1.0003x over previous
#include <cuda_runtime.h>

// YOLOV3TargetMerger: b=32, N=22743, M=50, C=80
// Inputs: 0 box_preds[b,N,4] 1 gt_boxes[b,M,4] 2 obj_t[b,N,1]
//         3 centers_t[b,N,2] 4 scales_t[b,N,2] 5 weights_t[b,N,2] 6 clas_t[b,N,80]
// Output (concat f32): obj[S], cen[2S], sca[2S], wei[2S], cls_t[80S], cls_m[80S]
//
// Converged structure: concurrent fork/join; total = ~640 MB DRAM traffic /
// achieved BW. This round: de-interleave the two class output streams per
// chunk (all out_t stores, then all out_m) for DRAM page locality.

#define BATCH 32
#define MGT   50
#define NCLS  80
#define C4    (NCLS / 4)
#define THR   0.7f
#define EPSF  1e-12f
#define CLS_THREADS 256
#define UNROLL 4
#define CHUNK (CLS_THREADS * UNROLL)   // 1024 float4 per block

__global__ void __launch_bounds__(256) merge_main_kernel(
    const float4* __restrict__ bp,
    const float4* __restrict__ gt,
    const float*  __restrict__ obj,
    const float2* __restrict__ cen,
    const float2* __restrict__ sca,
    const float2* __restrict__ wei,
    float* __restrict__ out,
    int N, long long S)
{
    __shared__ float4 sgt[MGT];
    __shared__ float  sarea[MGT];
    __shared__ int    scnt;

    const int b = blockIdx.y;
    const int t = threadIdx.x;

    // compact gt boxes: non-positive width/height => inter==0 vs every anchor,
    // which can never produce a hit (needs d>0, then 0 > 0.7*d is false).
    if (t == 0) scnt = 0;
    __syncthreads();
    if (t < MGT) {
        const float4 g = gt[b * MGT + t];
        if (g.z > g.x && g.w > g.y) {
            const int k = atomicAdd(&scnt, 1);
            sgt[k]   = g;
            sarea[k] = (g.z - g.x) * (g.w - g.y);
        }
    }
    __syncthreads();
    const int K = scnt;                       // ~12.5 expected

    const int n = blockIdx.x * blockDim.x + t;
    if (n >= N) return;
    const long long i = (long long)b * N + n;

    const float  o = obj[i];
    const float4 p = bp[i];
    const float2 c = cen[i];
    const float2 s = sca[i];
    const float2 w = wei[i];
    const bool mask = (o > 0.0f);

    float objout;
    if (mask) {
        objout = o;                           // IOU result unused -> skip loop
    } else {
        const float area_p = (p.z - p.x) * (p.w - p.y);

        bool hit = false, ambig = false;
        for (int m = 0; m < K; m++) {
            const float4 g = sgt[m];
            const float ww = fmaxf(fminf(p.z, g.z) - fmaxf(p.x, g.x), 0.0f);
            const float hh = fmaxf(fminf(p.w, g.w) - fmaxf(p.y, g.y), 0.0f);
            const float inter = ww * hh;
            float u = area_p + sarea[m];
            u = u - inter;
            const float d = u + EPSF;         // ref denominator, same op order
            const float thr  = THR * d;
            const float diff = inter - thr;
            const float marg = 1e-6f * thr;
            const bool pos = (d > 0.0f);
            hit   = hit   | (pos & (diff >  marg));
            ambig = ambig | (pos & (fabsf(diff) <= marg));
        }
        if (ambig) {                          // rare: redo exactly (IEEE div)
            hit = false;
            for (int m = 0; m < K; m++) {
                const float4 g = sgt[m];
                const float ww = fmaxf(fminf(p.z, g.z) - fmaxf(p.x, g.x), 0.0f);
                const float hh = fmaxf(fminf(p.w, g.w) - fmaxf(p.y, g.y), 0.0f);
                const float inter = ww * hh;
                float u = area_p + sarea[m];
                u = u - inter;
                const float d = u + EPSF;
                hit = hit | ((inter / d) > THR);  // d<0 -> iou<=0 -> false (== ref)
            }
        }
        objout = hit ? -1.0f : 0.0f;
    }

    out[i] = objout;

    const float2 z = make_float2(0.0f, 0.0f);
    ((float2*)(out + S     ))[i] = mask ? c : z;
    ((float2*)(out + 3 * S ))[i] = mask ? s : z;
    ((float2*)(out + 5 * S ))[i] = mask ? w : z;
}

// Flat grid, short-lived CTAs, 4 front-batched iterations per thread.
// Store streams de-interleaved per chunk for DRAM page locality.
__global__ void __launch_bounds__(CLS_THREADS) merge_class_kernel(
    const float*  __restrict__ obj,
    const float4* __restrict__ cls,
    float4* __restrict__ out_t,
    float4* __restrict__ out_m,
    int total4)   // = S * C4  (14.55M, fits int)
{
    const int base = blockIdx.x * CHUNK + threadIdx.x;

    if (base + (UNROLL - 1) * CLS_THREADS < total4) {
        // full chunk: no bounds checks
        bool   mk[UNROLL];
        float4 c[UNROLL];
#pragma unroll
        for (int j = 0; j < UNROLL; j++)
            mk[j] = (obj[(unsigned)(base + j * CLS_THREADS) / C4] > 0.0f);
#pragma unroll
        for (int j = 0; j < UNROLL; j++)
            c[j] = mk[j] ? __ldcs(&cls[base + j * CLS_THREADS])
                         : make_float4(-1.0f, -1.0f, -1.0f, -1.0f);

        // pass 1: all target stores (16KB contiguous per block)
#pragma unroll
        for (int j = 0; j < UNROLL; j++)
            __stcs(&out_t[base + j * CLS_THREADS], c[j]);

        // pass 2: all mask stores (16KB contiguous per block)
#pragma unroll
        for (int j = 0; j < UNROLL; j++) {
            float4 mv;
            if (mk[j]) {
                mv.x = (c[j].x >= 0.0f) ? 1.0f : 0.0f;
                mv.y = (c[j].y >= 0.0f) ? 1.0f : 0.0f;
                mv.z = (c[j].z >= 0.0f) ? 1.0f : 0.0f;
                mv.w = (c[j].w >= 0.0f) ? 1.0f : 0.0f;
            } else {
                mv = make_float4(0.0f, 0.0f, 0.0f, 0.0f);
            }
            __stcs(&out_m[base + j * CLS_THREADS], mv);
        }
    } else {
        // tail block
#pragma unroll
        for (int j = 0; j < UNROLL; j++) {
            const int idx = base + j * CLS_THREADS;
            if (idx >= total4) continue;
            const bool mask = (obj[(unsigned)idx / C4] > 0.0f);
            float4 tv, mv;
            if (mask) {
                const float4 cc = __ldcs(&cls[idx]);
                tv = cc;
                mv.x = (cc.x >= 0.0f) ? 1.0f : 0.0f;
                mv.y = (cc.y >= 0.0f) ? 1.0f : 0.0f;
                mv.z = (cc.z >= 0.0f) ? 1.0f : 0.0f;
                mv.w = (cc.w >= 0.0f) ? 1.0f : 0.0f;
            } else {
                tv = make_float4(-1.0f, -1.0f, -1.0f, -1.0f);
                mv = make_float4(0.0f, 0.0f, 0.0f, 0.0f);
            }
            __stcs(&out_t[idx], tv);
            __stcs(&out_m[idx], mv);
        }
    }
}

static cudaStream_t g_s2 = 0;
static cudaEvent_t  g_fork = 0, g_join = 0;

extern "C" void kernel_launch(void* const* d_in, const int* in_sizes, int n_in,
                              void* d_out, int out_size)
{
    const float4* bp  = (const float4*)d_in[0];
    const float4* gt  = (const float4*)d_in[1];
    const float*  obj = (const float*) d_in[2];
    const float2* cen = (const float2*)d_in[3];
    const float2* sca = (const float2*)d_in[4];
    const float2* wei = (const float2*)d_in[5];
    const float*  cls = (const float*) d_in[6];

    const long long S = in_sizes[2];      // b * N
    const int N = (int)(S / BATCH);
    float* out = (float*)d_out;

    if (g_s2 == 0) {
        cudaStreamCreateWithFlags(&g_s2, cudaStreamNonBlocking);
        cudaEventCreateWithFlags(&g_fork, cudaEventDisableTiming);
        cudaEventCreateWithFlags(&g_join, cudaEventDisableTiming);
    }

    // Fork: main kernel runs concurrently on g_s2 under the class stream.
    cudaEventRecord(g_fork, 0);
    cudaStreamWaitEvent(g_s2, g_fork, 0);

    {   // main path (small) — side stream
        dim3 block(256, 1, 1);
        dim3 grid((N + 255) / 256, BATCH, 1);
        merge_main_kernel<<<grid, block, 0, g_s2>>>(bp, gt, obj, cen, sca, wei,
                                                    out, N, S);
    }
    {   // class path (long pole) — capture/default stream
        const int total4 = (int)(S * C4);
        float4* out_t = (float4*)(out + 7LL  * S);
        float4* out_m = (float4*)(out + 87LL * S);
        const int blocks = (total4 + CHUNK - 1) / CHUNK;
        merge_class_kernel<<<blocks, CLS_THREADS>>>(obj, (const float4*)cls,
                                                    out_t, out_m, total4);
    }

    // Join: default stream waits for the side stream's kernel.
    cudaEventRecord(g_join, g_s2);
    cudaStreamWaitEvent(0, g_join, 0);
}